// round 2
// baseline (speedup 1.0000x reference)
#include <cuda_runtime.h>
#include <cstdint>

// ----------------------------------------------------------------------------
// MultiheadAttention forward, 3xTF32 tensor-core pipeline.
// Inputs (metadata order): key, value, query, mask(int32), Wk, bk, Wv, bv,
//                          Wq, bq, Wo, bo.
// Output d_out = [ cv (2*1024*1024 f32) | aw (2*16*1024*1024 f32) ].
//
// Pipeline:
//   1. gemm3x (NN) x3 : Q/K/V projections [2048,1024]x[1024,1024]+bias -> scratch
//   2. gemm3x (NT)    : per (b,h) scores S = Q K^T / 8 -> aw region (raw)
//   3. softmax_rows   : row softmax over klen with mask, in place on aw
//   4. gemm3x (NN)    : per (b,h) context = aw @ V -> scratch ctx
//   5. gemm3x (NN)    : cv = ctx @ Wo + bo -> d_out
//
// GEMMs use mma.sync.m16n8k8 tf32 with a hi/lo split (3xTF32) for ~fp32
// accuracy. Scratch lives in __device__ globals (no allocation).
// ----------------------------------------------------------------------------

#define NEG_INF_F (__int_as_float(0xff7fffff))   // -FLT_MAX == np.finfo(f32).min

static __device__ float g_q  [2048 * 1024];
static __device__ float g_k  [2048 * 1024];
static __device__ float g_v  [2048 * 1024];
static __device__ float g_ctx[2048 * 1024];

__device__ __forceinline__ uint32_t f2tf(float x) {
    uint32_t r;
    asm("cvt.rna.tf32.f32 %0, %1;" : "=r"(r) : "f"(x));
    return r;
}

__device__ __forceinline__ void mma8(float c[4], const uint32_t a[4],
                                     uint32_t b0, uint32_t b1) {
    asm volatile(
        "mma.sync.aligned.m16n8k8.row.col.f32.tf32.tf32.f32 "
        "{%0,%1,%2,%3},{%4,%5,%6,%7},{%8,%9},{%0,%1,%2,%3};"
        : "+f"(c[0]), "+f"(c[1]), "+f"(c[2]), "+f"(c[3])
        : "r"(a[0]), "r"(a[1]), "r"(a[2]), "r"(a[3]), "r"(b0), "r"(b1));
}

// C[M,N] = scale * A*op(B) + bias.   NT=false: B is [K,N] row-major (NN).
// NT=true : B is [N,K] row-major (C = A B^T).
// Per-z offsets: ptr += (z/H)*strideB + (z%H)*strideH  (z = blockIdx.z).
// All dims are multiples of the tile sizes (no guards needed for this problem).
template <int BM, int BN, bool NT, int NTHREADS>
__global__ __launch_bounds__(NTHREADS) void gemm3x(
    const float* __restrict__ A, long long aB, long long aH, int lda,
    const float* __restrict__ Bmat, long long bB, long long bH, int ldb,
    float* __restrict__ C, long long cB, long long cH, int ldc,
    int K, const float* __restrict__ bias, float scale, int H)
{
    constexpr int BK   = 32;
    constexpr int WARPS_M = BM / 64;     // warp tile 64x32
    constexpr int APAD = 36;             // BK + 4 pad (conflict-free frags)
    constexpr int BNP  = BN + 8;         // pad for NN B tile
    constexpr int ASZ  = BM * APAD;
    constexpr int BSZ  = NT ? BN * APAD : BK * BNP;

    extern __shared__ uint32_t smbuf[];
    uint32_t* sAh = smbuf;
    uint32_t* sAl = smbuf + ASZ;
    uint32_t* sBh = smbuf + 2 * ASZ;
    uint32_t* sBl = sBh + BSZ;

    const int z  = blockIdx.z;
    const int bb = z / H, hh = z - bb * H;
    const float* Ap = A + (long long)bb * aB + (long long)hh * aH
                        + (long long)blockIdx.y * BM * lda;
    const float* Bp;
    if (NT) Bp = Bmat + (long long)bb * bB + (long long)hh * bH
                      + (long long)blockIdx.x * BN * ldb;
    else    Bp = Bmat + (long long)bb * bB + (long long)hh * bH
                      + (long long)blockIdx.x * BN;
    float* Cp = C + (long long)bb * cB + (long long)hh * cH;

    const int tid  = threadIdx.x;
    const int lane = tid & 31;
    const int wid  = tid >> 5;
    const int wm   = (wid % WARPS_M) * 64;
    const int wn   = (wid / WARPS_M) * 32;

    float acc[4][4][4];
#pragma unroll
    for (int i = 0; i < 4; i++)
#pragma unroll
        for (int j = 0; j < 4; j++)
#pragma unroll
            for (int c = 0; c < 4; c++) acc[i][j][c] = 0.f;

    for (int k0 = 0; k0 < K; k0 += BK) {
        __syncthreads();
        // ---- load A tile [BM x 32], split into tf32 hi/lo ----
#pragma unroll
        for (int i = 0; i < (BM * 8) / NTHREADS; i++) {
            int t  = tid + i * NTHREADS;
            int r  = t >> 3;
            int c4 = (t & 7) * 4;
            float4 v = *(const float4*)(Ap + (long long)r * lda + k0 + c4);
            uint32_t h0 = f2tf(v.x), h1 = f2tf(v.y), h2 = f2tf(v.z), h3 = f2tf(v.w);
            uint32_t l0 = f2tf(v.x - __uint_as_float(h0));
            uint32_t l1 = f2tf(v.y - __uint_as_float(h1));
            uint32_t l2 = f2tf(v.z - __uint_as_float(h2));
            uint32_t l3 = f2tf(v.w - __uint_as_float(h3));
            int s = r * APAD + c4;
            *(uint4*)(sAh + s) = make_uint4(h0, h1, h2, h3);
            *(uint4*)(sAl + s) = make_uint4(l0, l1, l2, l3);
        }
        // ---- load B tile ----
        if (NT) {
#pragma unroll
            for (int i = 0; i < (BN * 8) / NTHREADS; i++) {
                int t  = tid + i * NTHREADS;
                int r  = t >> 3;
                int c4 = (t & 7) * 4;
                float4 v = *(const float4*)(Bp + (long long)r * ldb + k0 + c4);
                uint32_t h0 = f2tf(v.x), h1 = f2tf(v.y), h2 = f2tf(v.z), h3 = f2tf(v.w);
                uint32_t l0 = f2tf(v.x - __uint_as_float(h0));
                uint32_t l1 = f2tf(v.y - __uint_as_float(h1));
                uint32_t l2 = f2tf(v.z - __uint_as_float(h2));
                uint32_t l3 = f2tf(v.w - __uint_as_float(h3));
                int s = r * APAD + c4;
                *(uint4*)(sBh + s) = make_uint4(h0, h1, h2, h3);
                *(uint4*)(sBl + s) = make_uint4(l0, l1, l2, l3);
            }
        } else {
#pragma unroll
            for (int i = 0; i < (BN * 8) / NTHREADS; i++) {
                int t  = tid + i * NTHREADS;
                constexpr int C4 = BN / 4;
                int r  = t / C4;
                int c4 = (t - r * C4) * 4;
                float4 v = *(const float4*)(Bp + (long long)(k0 + r) * ldb + c4);
                uint32_t h0 = f2tf(v.x), h1 = f2tf(v.y), h2 = f2tf(v.z), h3 = f2tf(v.w);
                uint32_t l0 = f2tf(v.x - __uint_as_float(h0));
                uint32_t l1 = f2tf(v.y - __uint_as_float(h1));
                uint32_t l2 = f2tf(v.z - __uint_as_float(h2));
                uint32_t l3 = f2tf(v.w - __uint_as_float(h3));
                int s = r * BNP + c4;
                *(uint4*)(sBh + s) = make_uint4(h0, h1, h2, h3);
                *(uint4*)(sBl + s) = make_uint4(l0, l1, l2, l3);
            }
        }
        __syncthreads();

        // ---- compute: 4 k-steps of 8, warp tile 64x32 ----
#pragma unroll
        for (int ks = 0; ks < 4; ks++) {
            const int kb = ks * 8;
            uint32_t ah[4][4], al[4][4];
#pragma unroll
            for (int mt = 0; mt < 4; mt++) {
                int o = (wm + mt * 16 + (lane >> 2)) * APAD + kb + (lane & 3);
                ah[mt][0] = sAh[o];
                ah[mt][1] = sAh[o + 8 * APAD];
                ah[mt][2] = sAh[o + 4];
                ah[mt][3] = sAh[o + 8 * APAD + 4];
                al[mt][0] = sAl[o];
                al[mt][1] = sAl[o + 8 * APAD];
                al[mt][2] = sAl[o + 4];
                al[mt][3] = sAl[o + 8 * APAD + 4];
            }
            uint32_t bh[4][2], bl[4][2];
#pragma unroll
            for (int nt = 0; nt < 4; nt++) {
                int n  = wn + nt * 8 + (lane >> 2);
                int kk = kb + (lane & 3);
                if (NT) {
                    int o = n * APAD + kk;
                    bh[nt][0] = sBh[o];
                    bh[nt][1] = sBh[o + 4];
                    bl[nt][0] = sBl[o];
                    bl[nt][1] = sBl[o + 4];
                } else {
                    int o = kk * BNP + n;
                    bh[nt][0] = sBh[o];
                    bh[nt][1] = sBh[o + 4 * BNP];
                    bl[nt][0] = sBl[o];
                    bl[nt][1] = sBl[o + 4 * BNP];
                }
            }
#pragma unroll
            for (int mt = 0; mt < 4; mt++)
#pragma unroll
                for (int nt = 0; nt < 4; nt++) {
                    // small cross terms first, then hi*hi (3xTF32)
                    mma8(acc[mt][nt], ah[mt], bl[nt][0], bl[nt][1]);
                    mma8(acc[mt][nt], al[mt], bh[nt][0], bh[nt][1]);
                    mma8(acc[mt][nt], ah[mt], bh[nt][0], bh[nt][1]);
                }
        }
    }

    // ---- epilogue: scale + bias, float2 stores ----
    const int row0 = blockIdx.y * BM + wm;
    const int col0 = blockIdx.x * BN + wn;
#pragma unroll
    for (int mt = 0; mt < 4; mt++) {
#pragma unroll
        for (int nt = 0; nt < 4; nt++) {
            int r = row0 + mt * 16 + (lane >> 2);
            int c = col0 + nt * 8 + 2 * (lane & 3);
            float b0 = bias ? bias[c]     : 0.f;
            float b1 = bias ? bias[c + 1] : 0.f;
            float2 v0 = make_float2(acc[mt][nt][0] * scale + b0,
                                    acc[mt][nt][1] * scale + b1);
            float2 v1 = make_float2(acc[mt][nt][2] * scale + b0,
                                    acc[mt][nt][3] * scale + b1);
            *(float2*)(Cp + (long long)r * ldc + c)       = v0;
            *(float2*)(Cp + (long long)(r + 8) * ldc + c) = v1;
        }
    }
}

// One warp per row of 1024: masked max -> exp -> normalize, in place.
__global__ __launch_bounds__(256) void softmax_rows(
    float* __restrict__ aw, const int* __restrict__ mask)
{
    int gw   = (blockIdx.x * 256 + threadIdx.x) >> 5;   // row = (b*16+h)*1024+q
    int lane = threadIdx.x & 31;
    int q = gw & 1023;
    int b = gw >> 14;
    const int* mrow = mask + ((long long)(b * 1024 + q) << 10);
    float*     arow = aw + ((long long)gw << 10);

    float v[32];
    float m = NEG_INF_F;
#pragma unroll
    for (int j = 0; j < 8; j++) {
        int c = (lane + 32 * j) * 4;
        float4 f = *(const float4*)(arow + c);
        int4  mk = *(const int4*)(mrow + c);
        v[4 * j + 0] = mk.x ? f.x : NEG_INF_F;
        v[4 * j + 1] = mk.y ? f.y : NEG_INF_F;
        v[4 * j + 2] = mk.z ? f.z : NEG_INF_F;
        v[4 * j + 3] = mk.w ? f.w : NEG_INF_F;
        m = fmaxf(m, fmaxf(fmaxf(v[4 * j], v[4 * j + 1]),
                           fmaxf(v[4 * j + 2], v[4 * j + 3])));
    }
#pragma unroll
    for (int o = 16; o > 0; o >>= 1) m = fmaxf(m, __shfl_xor_sync(0xffffffffu, m, o));
    float s = 0.f;
#pragma unroll
    for (int i = 0; i < 32; i++) { float e = __expf(v[i] - m); v[i] = e; s += e; }
#pragma unroll
    for (int o = 16; o > 0; o >>= 1) s += __shfl_xor_sync(0xffffffffu, s, o);
    float inv = 1.f / s;
#pragma unroll
    for (int j = 0; j < 8; j++) {
        int c = (lane + 32 * j) * 4;
        *(float4*)(arow + c) = make_float4(v[4 * j] * inv, v[4 * j + 1] * inv,
                                           v[4 * j + 2] * inv, v[4 * j + 3] * inv);
    }
}

extern "C" void kernel_launch(void* const* d_in, const int* in_sizes, int n_in,
                              void* d_out, int out_size)
{
    const float* key   = (const float*)d_in[0];
    const float* value = (const float*)d_in[1];
    const float* query = (const float*)d_in[2];
    const int*   mask  = (const int*)d_in[3];
    const float* Wk = (const float*)d_in[4];
    const float* bk = (const float*)d_in[5];
    const float* Wv = (const float*)d_in[6];
    const float* bv = (const float*)d_in[7];
    const float* Wq = (const float*)d_in[8];
    const float* bq = (const float*)d_in[9];
    const float* Wo = (const float*)d_in[10];
    const float* bo = (const float*)d_in[11];

    float* cv = (float*)d_out;                    // [2, 1024, 1024]
    float* aw = cv + 2LL * 1024 * 1024;           // [2, 16, 1024, 1024]

    float *gq, *gk, *gv, *gc;
    cudaGetSymbolAddress((void**)&gq, g_q);
    cudaGetSymbolAddress((void**)&gk, g_k);
    cudaGetSymbolAddress((void**)&gv, g_v);
    cudaGetSymbolAddress((void**)&gc, g_ctx);

    // opt-in to >48KB dynamic smem (idempotent; executes outside stream work)
    cudaFuncSetAttribute((const void*)gemm3x<128, 128, false, 256>,
                         cudaFuncAttributeMaxDynamicSharedMemorySize, 71680);
    cudaFuncSetAttribute((const void*)gemm3x<128, 128, true, 256>,
                         cudaFuncAttributeMaxDynamicSharedMemorySize, 73728);
    cudaFuncSetAttribute((const void*)gemm3x<128, 64, false, 128>,
                         cudaFuncAttributeMaxDynamicSharedMemorySize, 55296);

    // 1) projections: [2048,1024] @ [1024,1024] + bias
    gemm3x<128, 128, false, 256><<<dim3(8, 16, 1), 256, 71680>>>(
        query, 0, 0, 1024, Wq, 0, 0, 1024, gq, 0, 0, 1024, 1024, bq, 1.f, 1);
    gemm3x<128, 128, false, 256><<<dim3(8, 16, 1), 256, 71680>>>(
        key,   0, 0, 1024, Wk, 0, 0, 1024, gk, 0, 0, 1024, 1024, bk, 1.f, 1);
    gemm3x<128, 128, false, 256><<<dim3(8, 16, 1), 256, 71680>>>(
        value, 0, 0, 1024, Wv, 0, 0, 1024, gv, 0, 0, 1024, 1024, bv, 1.f, 1);

    // 2) scores per (b,h): S = Q K^T / 8 -> aw raw
    gemm3x<128, 128, true, 256><<<dim3(8, 8, 32), 256, 73728>>>(
        gq, 1048576, 64, 1024,
        gk, 1048576, 64, 1024,
        aw, 16777216LL, 1048576LL, 1024,
        64, nullptr, 0.125f, 16);

    // 3) masked softmax rows, in place (32768 rows, 8 warps/block)
    softmax_rows<<<4096, 256>>>(aw, mask);

    // 4) context per (b,h): ctx = aw @ V
    gemm3x<128, 64, false, 128><<<dim3(1, 8, 32), 128, 55296>>>(
        aw, 16777216LL, 1048576LL, 1024,
        gv, 1048576, 64, 1024,
        gc, 1048576, 64, 1024,
        1024, nullptr, 1.f, 16);

    // 5) output projection: cv = ctx @ Wo + bo
    gemm3x<128, 128, false, 256><<<dim3(8, 16, 1), 256, 71680>>>(
        gc, 0, 0, 1024, Wo, 0, 0, 1024, cv, 0, 0, 1024, 1024, bo, 1.f, 1);
}

// round 3
// speedup vs baseline: 1.4014x; 1.4014x over previous
#include <cuda_runtime.h>
#include <cstdint>

// ----------------------------------------------------------------------------
// MultiheadAttention forward — 2xTF32 tensor-core pipeline, cp.async 3-stage.
//   1. gemm2x (NN) x3 : Q/K/V projections + bias -> scratch
//   2. gemm2x (NT)    : per (b,h) scores S = Q K^T / 8 -> aw region (raw)
//   3. softmax_rows   : block per (b,q), mask in smem, 16 warps = 16 heads
//   4. gemm2x (NN)    : per (b,h) context = aw @ V -> scratch
//   5. gemm2x (NN)    : cv = ctx @ Wo + bo -> d_out
// smem tiles are raw fp32 (cp.async 16B), split to tf32 hi/lo at fragment load.
// ----------------------------------------------------------------------------

#define NEG_INF_F (__int_as_float(0xff7fffff))   // -FLT_MAX

static __device__ float g_q  [2048 * 1024];
static __device__ float g_k  [2048 * 1024];
static __device__ float g_v  [2048 * 1024];
static __device__ float g_ctx[2048 * 1024];

__device__ __forceinline__ uint32_t f2tf(float x) {
    uint32_t r;
    asm("cvt.rna.tf32.f32 %0, %1;" : "=r"(r) : "f"(x));
    return r;
}

__device__ __forceinline__ uint32_t s2u(const void* p) {
    return (uint32_t)__cvta_generic_to_shared(p);
}

#define CP_ASYNC16(dst, src) \
    asm volatile("cp.async.cg.shared.global [%0], [%1], 16;" :: "r"(dst), "l"(src))
#define CP_COMMIT() asm volatile("cp.async.commit_group;")
#define CP_WAIT1()  asm volatile("cp.async.wait_group 1;")

__device__ __forceinline__ void mma8(float c[4], const uint32_t a[4],
                                     uint32_t b0, uint32_t b1) {
    asm volatile(
        "mma.sync.aligned.m16n8k8.row.col.f32.tf32.tf32.f32 "
        "{%0,%1,%2,%3},{%4,%5,%6,%7},{%8,%9},{%0,%1,%2,%3};"
        : "+f"(c[0]), "+f"(c[1]), "+f"(c[2]), "+f"(c[3])
        : "r"(a[0]), "r"(a[1]), "r"(a[2]), "r"(a[3]), "r"(b0), "r"(b1));
}

// C[M,N] = scale*A*op(B) + bias.  NT=false: B [K,N] row-major; NT=true: B [N,K].
// Per-z offsets: z = blockIdx.z -> (b = z/H, h = z%H).
template <int BM, int BN, bool NT, int NTHREADS>
__global__ __launch_bounds__(NTHREADS) void gemm2x(
    const float* __restrict__ A, long long aB, long long aH, int lda,
    const float* __restrict__ Bmat, long long bB, long long bH, int ldb,
    float* __restrict__ C, long long cB, long long cH, int ldc,
    int K, const float* __restrict__ bias, float scale, int H)
{
    constexpr int BK = 32, STAGES = 3;
    constexpr int WARPS_M = BM / 64;          // warp tile 64x32
    constexpr int AP  = 36;                   // fp32 row pad (conflict-free)
    constexpr int BNP = BN + 4;
    constexpr int ASZ = BM * AP;
    constexpr int BSZ = NT ? BN * AP : BK * BNP;

    extern __shared__ float sm[];
    float* sA = sm;
    float* sB = sm + STAGES * ASZ;

    const int z  = blockIdx.z;
    const int bb = z / H, hh = z - bb * H;
    const float* Ap = A + (long long)bb * aB + (long long)hh * aH
                        + (long long)blockIdx.y * BM * lda;
    const float* Bp;
    if (NT) Bp = Bmat + (long long)bb * bB + (long long)hh * bH
                      + (long long)blockIdx.x * BN * ldb;
    else    Bp = Bmat + (long long)bb * bB + (long long)hh * bH
                      + (long long)blockIdx.x * BN;
    float* Cp = C + (long long)bb * cB + (long long)hh * cH;

    const int tid  = threadIdx.x;
    const int lane = tid & 31;
    const int wid  = tid >> 5;
    const int wm   = (wid % WARPS_M) * 64;
    const int wn   = (wid / WARPS_M) * 32;

    float acc[4][4][4];
#pragma unroll
    for (int i = 0; i < 4; i++)
#pragma unroll
        for (int j = 0; j < 4; j++)
#pragma unroll
            for (int c = 0; c < 4; c++) acc[i][j][c] = 0.f;

    auto load_tile = [&](int slot, int k0) {
        float* dA = sA + slot * ASZ;
        float* dB = sB + slot * BSZ;
#pragma unroll
        for (int i = 0; i < (BM * 8) / NTHREADS; i++) {
            int t = tid + i * NTHREADS;
            int r = t >> 3, c4 = (t & 7) * 4;
            CP_ASYNC16(s2u(dA + r * AP + c4), Ap + (long long)r * lda + k0 + c4);
        }
        if (NT) {
#pragma unroll
            for (int i = 0; i < (BN * 8) / NTHREADS; i++) {
                int t = tid + i * NTHREADS;
                int r = t >> 3, c4 = (t & 7) * 4;
                CP_ASYNC16(s2u(dB + r * AP + c4), Bp + (long long)r * ldb + k0 + c4);
            }
        } else {
#pragma unroll
            for (int i = 0; i < (BN * 8) / NTHREADS; i++) {
                int t = tid + i * NTHREADS;
                constexpr int C4 = BN / 4;
                int r = t / C4, c4 = (t - r * C4) * 4;
                CP_ASYNC16(s2u(dB + r * BNP + c4), Bp + (long long)(k0 + r) * ldb + c4);
            }
        }
    };

    auto compute = [&](int slot) {
        const float* cA = sA + slot * ASZ;
        const float* cB = sB + slot * BSZ;
#pragma unroll
        for (int ks = 0; ks < 4; ks++) {
            const int kb = ks * 8;
            uint32_t ah[4][4], al[4][4];
#pragma unroll
            for (int mt = 0; mt < 4; mt++) {
                int o = (wm + mt * 16 + (lane >> 2)) * AP + kb + (lane & 3);
                float f0 = cA[o];
                float f1 = cA[o + 8 * AP];
                float f2 = cA[o + 4];
                float f3 = cA[o + 8 * AP + 4];
                ah[mt][0] = f2tf(f0); al[mt][0] = f2tf(f0 - __uint_as_float(ah[mt][0]));
                ah[mt][1] = f2tf(f1); al[mt][1] = f2tf(f1 - __uint_as_float(ah[mt][1]));
                ah[mt][2] = f2tf(f2); al[mt][2] = f2tf(f2 - __uint_as_float(ah[mt][2]));
                ah[mt][3] = f2tf(f3); al[mt][3] = f2tf(f3 - __uint_as_float(ah[mt][3]));
            }
            uint32_t bh[4][2];
#pragma unroll
            for (int nt = 0; nt < 4; nt++) {
                int n  = wn + nt * 8 + (lane >> 2);
                int kk = kb + (lane & 3);
                if (NT) {
                    int o = n * AP + kk;
                    bh[nt][0] = f2tf(cB[o]);
                    bh[nt][1] = f2tf(cB[o + 4]);
                } else {
                    int o = kk * BNP + n;
                    bh[nt][0] = f2tf(cB[o]);
                    bh[nt][1] = f2tf(cB[o + 4 * BNP]);
                }
            }
#pragma unroll
            for (int mt = 0; mt < 4; mt++)
#pragma unroll
                for (int nt = 0; nt < 4; nt++) {
                    mma8(acc[mt][nt], al[mt], bh[nt][0], bh[nt][1]);  // low correction
                    mma8(acc[mt][nt], ah[mt], bh[nt][0], bh[nt][1]);  // main term
                }
        }
    };

    const int kt_n = K / BK;
#pragma unroll
    for (int s = 0; s < STAGES - 1; s++) {
        if (s < kt_n) load_tile(s, s * BK);
        CP_COMMIT();
    }
    for (int kt = 0; kt < kt_n; kt++) {
        CP_WAIT1();
        __syncthreads();
        int nk = kt + STAGES - 1;
        if (nk < kt_n) load_tile(nk % STAGES, nk * BK);
        CP_COMMIT();
        compute(kt % STAGES);
    }

    // ---- epilogue ----
    const int row0 = blockIdx.y * BM + wm;
    const int col0 = blockIdx.x * BN + wn;
#pragma unroll
    for (int mt = 0; mt < 4; mt++) {
#pragma unroll
        for (int nt = 0; nt < 4; nt++) {
            int r = row0 + mt * 16 + (lane >> 2);
            int c = col0 + nt * 8 + 2 * (lane & 3);
            float b0 = bias ? bias[c]     : 0.f;
            float b1 = bias ? bias[c + 1] : 0.f;
            float2 v0 = make_float2(acc[mt][nt][0] * scale + b0,
                                    acc[mt][nt][1] * scale + b1);
            float2 v1 = make_float2(acc[mt][nt][2] * scale + b0,
                                    acc[mt][nt][3] * scale + b1);
            *(float2*)(Cp + (long long)r * ldc + c)       = v0;
            *(float2*)(Cp + (long long)(r + 8) * ldc + c) = v1;
        }
    }
}

// Block = one (b,q); mask row staged in smem; 16 warps cover the 16 heads.
__global__ __launch_bounds__(512) void softmax_rows(
    float* __restrict__ aw, const int* __restrict__ mask)
{
    __shared__ int smask[1024];
    const int bq = blockIdx.x;                 // b*1024 + q
    const int b  = bq >> 10, q = bq & 1023;
    const int* mrow = mask + ((long long)bq << 10);
    if (threadIdx.x < 256)
        ((int4*)smask)[threadIdx.x] = ((const int4*)mrow)[threadIdx.x];
    __syncthreads();

    const int h    = threadIdx.x >> 5;
    const int lane = threadIdx.x & 31;
    float* arow = aw + ((long long)((b * 16 + h) * 1024 + q) << 10);

    float v[32];
    float m = NEG_INF_F;
#pragma unroll
    for (int j = 0; j < 8; j++) {
        int c = (lane + 32 * j) * 4;
        float4 f = *(const float4*)(arow + c);
        int4  mk = *(const int4*)(smask + c);
        v[4 * j + 0] = mk.x ? f.x : NEG_INF_F;
        v[4 * j + 1] = mk.y ? f.y : NEG_INF_F;
        v[4 * j + 2] = mk.z ? f.z : NEG_INF_F;
        v[4 * j + 3] = mk.w ? f.w : NEG_INF_F;
        m = fmaxf(m, fmaxf(fmaxf(v[4 * j], v[4 * j + 1]),
                           fmaxf(v[4 * j + 2], v[4 * j + 3])));
    }
#pragma unroll
    for (int o = 16; o > 0; o >>= 1) m = fmaxf(m, __shfl_xor_sync(0xffffffffu, m, o));
    float s = 0.f;
#pragma unroll
    for (int i = 0; i < 32; i++) { float e = __expf(v[i] - m); v[i] = e; s += e; }
#pragma unroll
    for (int o = 16; o > 0; o >>= 1) s += __shfl_xor_sync(0xffffffffu, s, o);
    float inv = 1.f / s;
#pragma unroll
    for (int j = 0; j < 8; j++) {
        int c = (lane + 32 * j) * 4;
        *(float4*)(arow + c) = make_float4(v[4 * j] * inv, v[4 * j + 1] * inv,
                                           v[4 * j + 2] * inv, v[4 * j + 3] * inv);
    }
}

extern "C" void kernel_launch(void* const* d_in, const int* in_sizes, int n_in,
                              void* d_out, int out_size)
{
    const float* key   = (const float*)d_in[0];
    const float* value = (const float*)d_in[1];
    const float* query = (const float*)d_in[2];
    const int*   mask  = (const int*)d_in[3];
    const float* Wk = (const float*)d_in[4];
    const float* bk = (const float*)d_in[5];
    const float* Wv = (const float*)d_in[6];
    const float* bv = (const float*)d_in[7];
    const float* Wq = (const float*)d_in[8];
    const float* bq = (const float*)d_in[9];
    const float* Wo = (const float*)d_in[10];
    const float* bo = (const float*)d_in[11];

    float* cv = (float*)d_out;                    // [2, 1024, 1024]
    float* aw = cv + 2LL * 1024 * 1024;           // [2, 16, 1024, 1024]

    float *gq, *gk, *gv, *gc;
    cudaGetSymbolAddress((void**)&gq, g_q);
    cudaGetSymbolAddress((void**)&gk, g_k);
    cudaGetSymbolAddress((void**)&gv, g_v);
    cudaGetSymbolAddress((void**)&gc, g_ctx);

    // smem: NN128 = 3*(128*36 + 32*132)*4 = 105984
    //       NT128 = 3*(128*36 + 128*36)*4 = 110592
    //       NN64  = 3*(128*36 + 32*68)*4  = 81408
    cudaFuncSetAttribute((const void*)gemm2x<128, 128, false, 256>,
                         cudaFuncAttributeMaxDynamicSharedMemorySize, 105984);
    cudaFuncSetAttribute((const void*)gemm2x<128, 128, true, 256>,
                         cudaFuncAttributeMaxDynamicSharedMemorySize, 110592);
    cudaFuncSetAttribute((const void*)gemm2x<128, 64, false, 128>,
                         cudaFuncAttributeMaxDynamicSharedMemorySize, 81408);

    // 1) projections: [2048,1024] @ [1024,1024] + bias
    gemm2x<128, 128, false, 256><<<dim3(8, 16, 1), 256, 105984>>>(
        query, 0, 0, 1024, Wq, 0, 0, 1024, gq, 0, 0, 1024, 1024, bq, 1.f, 1);
    gemm2x<128, 128, false, 256><<<dim3(8, 16, 1), 256, 105984>>>(
        key,   0, 0, 1024, Wk, 0, 0, 1024, gk, 0, 0, 1024, 1024, bk, 1.f, 1);
    gemm2x<128, 128, false, 256><<<dim3(8, 16, 1), 256, 105984>>>(
        value, 0, 0, 1024, Wv, 0, 0, 1024, gv, 0, 0, 1024, 1024, bv, 1.f, 1);

    // 2) scores per (b,h): S = Q K^T / 8 -> aw raw
    gemm2x<128, 128, true, 256><<<dim3(8, 8, 32), 256, 110592>>>(
        gq, 1048576, 64, 1024,
        gk, 1048576, 64, 1024,
        aw, 16777216LL, 1048576LL, 1024,
        64, nullptr, 0.125f, 16);

    // 3) masked softmax (2048 blocks = one per (b,q), 16 warps = heads)
    softmax_rows<<<2048, 512>>>(aw, mask);

    // 4) context per (b,h): ctx = aw @ V
    gemm2x<128, 64, false, 128><<<dim3(1, 8, 32), 128, 81408>>>(
        aw, 16777216LL, 1048576LL, 1024,
        gv, 1048576, 64, 1024,
        gc, 1048576, 64, 1024,
        1024, nullptr, 1.f, 16);

    // 5) output projection: cv = ctx @ Wo + bo
    gemm2x<128, 128, false, 256><<<dim3(8, 16, 1), 256, 105984>>>(
        gc, 0, 0, 1024, Wo, 0, 0, 1024, cv, 0, 0, 1024, 1024, bo, 1.f, 1);
}

// round 4
// speedup vs baseline: 1.5975x; 1.1400x over previous
#include <cuda_runtime.h>
#include <cstdint>

// ----------------------------------------------------------------------------
// MultiheadAttention forward — 2xTF32, conversion-free inner loop.
//  - B-side operands pre-rounded to tf32 (prep kernel for weights; projection
//    epilogue cvt for K/V)  -> B fragments load raw.
//  - A-side split by bitmask (LOP3+FSUB), fed raw (HW truncates to tf32).
//  - cp.async 3-stage pipeline, 2 blocks/SM, split-K=2 for the context GEMM.
// ----------------------------------------------------------------------------

#define NEG_INF_F (__int_as_float(0xff7fffff))   // -FLT_MAX

static __device__ float g_q   [2048 * 1024];
static __device__ float g_k   [2048 * 1024];
static __device__ float g_v   [2048 * 1024];
static __device__ float g_ctx [2048 * 1024];
static __device__ float g_cp  [2 * 2048 * 1024];   // split-K partials
static __device__ float g_wq  [1024 * 1024];
static __device__ float g_wk  [1024 * 1024];
static __device__ float g_wv  [1024 * 1024];
static __device__ float g_wo  [1024 * 1024];

__device__ __forceinline__ uint32_t f2tf(float x) {
    uint32_t r;
    asm("cvt.rna.tf32.f32 %0, %1;" : "=r"(r) : "f"(x));
    return r;
}
__device__ __forceinline__ uint32_t s2u(const void* p) {
    return (uint32_t)__cvta_generic_to_shared(p);
}

#define CP_ASYNC16(dst, src) \
    asm volatile("cp.async.cg.shared.global [%0], [%1], 16;" :: "r"(dst), "l"(src))
#define CP_COMMIT() asm volatile("cp.async.commit_group;")
#define CP_WAIT1()  asm volatile("cp.async.wait_group 1;")

__device__ __forceinline__ void mma8(float c[4], const uint32_t a[4],
                                     uint32_t b0, uint32_t b1) {
    asm volatile(
        "mma.sync.aligned.m16n8k8.row.col.f32.tf32.tf32.f32 "
        "{%0,%1,%2,%3},{%4,%5,%6,%7},{%8,%9},{%0,%1,%2,%3};"
        : "+f"(c[0]), "+f"(c[1]), "+f"(c[2]), "+f"(c[3])
        : "r"(a[0]), "r"(a[1]), "r"(a[2]), "r"(a[3]), "r"(b0), "r"(b1));
}

// Round 4 weight matrices (1M floats each) to tf32 once.
__global__ __launch_bounds__(256) void round4(
    const float* __restrict__ a, const float* __restrict__ b,
    const float* __restrict__ c, const float* __restrict__ d,
    float* __restrict__ oa, float* __restrict__ ob,
    float* __restrict__ oc, float* __restrict__ od)
{
    int i = blockIdx.x * 256 + threadIdx.x;          // < 262144 float4s
    float4 va = ((const float4*)a)[i];
    float4 vb = ((const float4*)b)[i];
    float4 vc = ((const float4*)c)[i];
    float4 vd = ((const float4*)d)[i];
#define R4(v) v.x = __uint_as_float(f2tf(v.x)); v.y = __uint_as_float(f2tf(v.y)); \
              v.z = __uint_as_float(f2tf(v.z)); v.w = __uint_as_float(f2tf(v.w));
    R4(va) R4(vb) R4(vc) R4(vd)
#undef R4
    ((float4*)oa)[i] = va; ((float4*)ob)[i] = vb;
    ((float4*)oc)[i] = vc; ((float4*)od)[i] = vd;
}

// C = scale*A*op(B) + bias. NT=false: B [K,N] row-major; NT=true: B [N,K].
// z -> (s = z/ZBH, r = z%ZBH, b = r/H, h = r%H); s adds split-K offsets.
// B operand must be pre-rounded to tf32. ROUND: round C to tf32 on store.
template <int BM, int BN, bool NT, int NTHREADS, bool ROUND>
__global__ __launch_bounds__(NTHREADS, 2) void gemm2x(
    const float* __restrict__ A, long long aB, long long aH, long long aS, int lda,
    const float* __restrict__ Bmat, long long bB, long long bH, long long bS, int ldb,
    float* __restrict__ C, long long cB, long long cH, long long cS, int ldc,
    int K, const float* __restrict__ bias, float scale, int H, int ZBH)
{
    constexpr int BK = 32, STAGES = 3;
    constexpr int WARPS_M = BM / 64;          // warp tile 64x32
    constexpr int AP  = 36;
    constexpr int BNP = BN + 4;
    constexpr int ASZ = BM * AP;
    constexpr int BSZ = NT ? BN * AP : BK * BNP;

    extern __shared__ float sm[];
    float* sA = sm;
    float* sB = sm + STAGES * ASZ;

    const int z = blockIdx.z;
    const int s  = z / ZBH;
    const int r0 = z - s * ZBH;
    const int bb = r0 / H, hh = r0 - bb * H;
    const float* Ap = A + (long long)bb * aB + (long long)hh * aH + (long long)s * aS
                        + (long long)blockIdx.y * BM * lda;
    const float* Bp;
    if (NT) Bp = Bmat + (long long)bb * bB + (long long)hh * bH + (long long)s * bS
                      + (long long)blockIdx.x * BN * ldb;
    else    Bp = Bmat + (long long)bb * bB + (long long)hh * bH + (long long)s * bS
                      + (long long)blockIdx.x * BN;
    float* Cp = C + (long long)bb * cB + (long long)hh * cH + (long long)s * cS;

    const int tid  = threadIdx.x;
    const int lane = tid & 31;
    const int wid  = tid >> 5;
    const int wm   = (wid % WARPS_M) * 64;
    const int wn   = (wid / WARPS_M) * 32;

    float acc[4][4][4];
#pragma unroll
    for (int i = 0; i < 4; i++)
#pragma unroll
        for (int j = 0; j < 4; j++)
#pragma unroll
            for (int c = 0; c < 4; c++) acc[i][j][c] = 0.f;

    auto load_tile = [&](int slot, int k0) {
        float* dA = sA + slot * ASZ;
        float* dB = sB + slot * BSZ;
#pragma unroll
        for (int i = 0; i < (BM * 8) / NTHREADS; i++) {
            int t = tid + i * NTHREADS;
            int r = t >> 3, c4 = (t & 7) * 4;
            CP_ASYNC16(s2u(dA + r * AP + c4), Ap + (long long)r * lda + k0 + c4);
        }
        if (NT) {
#pragma unroll
            for (int i = 0; i < (BN * 8) / NTHREADS; i++) {
                int t = tid + i * NTHREADS;
                int r = t >> 3, c4 = (t & 7) * 4;
                CP_ASYNC16(s2u(dB + r * AP + c4), Bp + (long long)r * ldb + k0 + c4);
            }
        } else {
#pragma unroll
            for (int i = 0; i < (BN * 8) / NTHREADS; i++) {
                int t = tid + i * NTHREADS;
                constexpr int C4 = BN / 4;
                int r = t / C4, c4 = (t - r * C4) * 4;
                CP_ASYNC16(s2u(dB + r * BNP + c4), Bp + (long long)(k0 + r) * ldb + c4);
            }
        }
    };

    auto compute = [&](int slot) {
        const float* cA = sA + slot * ASZ;
        const float* cB = sB + slot * BSZ;
#pragma unroll
        for (int ks = 0; ks < 4; ks++) {
            const int kb = ks * 8;
            uint32_t ah[4][4], al[4][4];
#pragma unroll
            for (int mt = 0; mt < 4; mt++) {
                int o = (wm + mt * 16 + (lane >> 2)) * AP + kb + (lane & 3);
#pragma unroll
                for (int e = 0; e < 4; e++) {
                    int oo = o + (e & 1) * 8 * AP + (e >> 1) * 4;
                    float f = cA[oo];
                    uint32_t h = __float_as_uint(f) & 0xffffe000u;
                    ah[mt][e] = h;
                    al[mt][e] = __float_as_uint(f - __uint_as_float(h));
                }
            }
            uint32_t bh[4][2];
#pragma unroll
            for (int nt = 0; nt < 4; nt++) {
                int n  = wn + nt * 8 + (lane >> 2);
                int kk = kb + (lane & 3);
                if (NT) {
                    int o = n * AP + kk;
                    bh[nt][0] = __float_as_uint(cB[o]);
                    bh[nt][1] = __float_as_uint(cB[o + 4]);
                } else {
                    int o = kk * BNP + n;
                    bh[nt][0] = __float_as_uint(cB[o]);
                    bh[nt][1] = __float_as_uint(cB[o + 4 * BNP]);
                }
            }
#pragma unroll
            for (int mt = 0; mt < 4; mt++)
#pragma unroll
                for (int nt = 0; nt < 4; nt++) {
                    mma8(acc[mt][nt], al[mt], bh[nt][0], bh[nt][1]);  // low term
                    mma8(acc[mt][nt], ah[mt], bh[nt][0], bh[nt][1]);  // main term
                }
        }
    };

    const int kt_n = K / BK;
#pragma unroll
    for (int st = 0; st < STAGES - 1; st++) {
        if (st < kt_n) load_tile(st, st * BK);
        CP_COMMIT();
    }
    for (int kt = 0; kt < kt_n; kt++) {
        CP_WAIT1();
        __syncthreads();
        int nk = kt + STAGES - 1;
        if (nk < kt_n) load_tile(nk % STAGES, nk * BK);
        CP_COMMIT();
        compute(kt % STAGES);
    }

    const int row0 = blockIdx.y * BM + wm;
    const int col0 = blockIdx.x * BN + wn;
#pragma unroll
    for (int mt = 0; mt < 4; mt++) {
#pragma unroll
        for (int nt = 0; nt < 4; nt++) {
            int r = row0 + mt * 16 + (lane >> 2);
            int c = col0 + nt * 8 + 2 * (lane & 3);
            float b0 = bias ? bias[c]     : 0.f;
            float b1 = bias ? bias[c + 1] : 0.f;
            float o0 = acc[mt][nt][0] * scale + b0;
            float o1 = acc[mt][nt][1] * scale + b1;
            float o2 = acc[mt][nt][2] * scale + b0;
            float o3 = acc[mt][nt][3] * scale + b1;
            if (ROUND) {
                o0 = __uint_as_float(f2tf(o0));
                o1 = __uint_as_float(f2tf(o1));
                o2 = __uint_as_float(f2tf(o2));
                o3 = __uint_as_float(f2tf(o3));
            }
            *(float2*)(Cp + (long long)r * ldc + c)       = make_float2(o0, o1);
            *(float2*)(Cp + (long long)(r + 8) * ldc + c) = make_float2(o2, o3);
        }
    }
}

// Block = one (b,q); mask row in smem; 16 warps = 16 heads. Streaming hints.
__global__ __launch_bounds__(512) void softmax_rows(
    float* __restrict__ aw, const int* __restrict__ mask)
{
    __shared__ int smask[1024];
    const int bq = blockIdx.x;                 // b*1024 + q
    const int b  = bq >> 10, q = bq & 1023;
    const int* mrow = mask + ((long long)bq << 10);
    if (threadIdx.x < 256)
        ((int4*)smask)[threadIdx.x] = ((const int4*)mrow)[threadIdx.x];
    __syncthreads();

    const int h    = threadIdx.x >> 5;
    const int lane = threadIdx.x & 31;
    float* arow = aw + ((long long)((b * 16 + h) * 1024 + q) << 10);

    float v[32];
    float m = NEG_INF_F;
#pragma unroll
    for (int j = 0; j < 8; j++) {
        int c = (lane + 32 * j) * 4;
        float4 f = __ldcs((const float4*)(arow + c));
        int4  mk = *(const int4*)(smask + c);
        v[4 * j + 0] = mk.x ? f.x : NEG_INF_F;
        v[4 * j + 1] = mk.y ? f.y : NEG_INF_F;
        v[4 * j + 2] = mk.z ? f.z : NEG_INF_F;
        v[4 * j + 3] = mk.w ? f.w : NEG_INF_F;
        m = fmaxf(m, fmaxf(fmaxf(v[4 * j], v[4 * j + 1]),
                           fmaxf(v[4 * j + 2], v[4 * j + 3])));
    }
#pragma unroll
    for (int o = 16; o > 0; o >>= 1) m = fmaxf(m, __shfl_xor_sync(0xffffffffu, m, o));
    float s = 0.f;
#pragma unroll
    for (int i = 0; i < 32; i++) { float e = __expf(v[i] - m); v[i] = e; s += e; }
#pragma unroll
    for (int o = 16; o > 0; o >>= 1) s += __shfl_xor_sync(0xffffffffu, s, o);
    float inv = 1.f / s;
#pragma unroll
    for (int j = 0; j < 8; j++) {
        int c = (lane + 32 * j) * 4;
        __stcs((float4*)(arow + c),
               make_float4(v[4 * j] * inv, v[4 * j + 1] * inv,
                           v[4 * j + 2] * inv, v[4 * j + 3] * inv));
    }
}

// ctx = partial0 + partial1 (split-K reduce), 2M floats.
__global__ __launch_bounds__(256) void addhalves(
    const float* __restrict__ p, float* __restrict__ ctx)
{
    int i = blockIdx.x * 256 + threadIdx.x;    // < 524288 float4s
    float4 a = ((const float4*)p)[i];
    float4 b = ((const float4*)(p + 2097152))[i];
    ((float4*)ctx)[i] = make_float4(a.x + b.x, a.y + b.y, a.z + b.z, a.w + b.w);
}

extern "C" void kernel_launch(void* const* d_in, const int* in_sizes, int n_in,
                              void* d_out, int out_size)
{
    const float* key   = (const float*)d_in[0];
    const float* value = (const float*)d_in[1];
    const float* query = (const float*)d_in[2];
    const int*   mask  = (const int*)d_in[3];
    const float* Wk = (const float*)d_in[4];
    const float* bk = (const float*)d_in[5];
    const float* Wv = (const float*)d_in[6];
    const float* bv = (const float*)d_in[7];
    const float* Wq = (const float*)d_in[8];
    const float* bq = (const float*)d_in[9];
    const float* Wo = (const float*)d_in[10];
    const float* bo = (const float*)d_in[11];

    float* cv = (float*)d_out;                    // [2, 1024, 1024]
    float* aw = cv + 2LL * 1024 * 1024;           // [2, 16, 1024, 1024]

    float *gq, *gk, *gv, *gc, *gp, *wqr, *wkr, *wvr, *wor;
    cudaGetSymbolAddress((void**)&gq,  g_q);
    cudaGetSymbolAddress((void**)&gk,  g_k);
    cudaGetSymbolAddress((void**)&gv,  g_v);
    cudaGetSymbolAddress((void**)&gc,  g_ctx);
    cudaGetSymbolAddress((void**)&gp,  g_cp);
    cudaGetSymbolAddress((void**)&wqr, g_wq);
    cudaGetSymbolAddress((void**)&wkr, g_wk);
    cudaGetSymbolAddress((void**)&wvr, g_wv);
    cudaGetSymbolAddress((void**)&wor, g_wo);

    cudaFuncSetAttribute((const void*)gemm2x<128, 128, false, 256, false>,
                         cudaFuncAttributeMaxDynamicSharedMemorySize, 105984);
    cudaFuncSetAttribute((const void*)gemm2x<128, 128, false, 256, true>,
                         cudaFuncAttributeMaxDynamicSharedMemorySize, 105984);
    cudaFuncSetAttribute((const void*)gemm2x<128, 128, true, 256, false>,
                         cudaFuncAttributeMaxDynamicSharedMemorySize, 110592);
    cudaFuncSetAttribute((const void*)gemm2x<128, 64, false, 128, false>,
                         cudaFuncAttributeMaxDynamicSharedMemorySize, 81408);

    // 0) round weights to tf32 once
    round4<<<1024, 256>>>(Wq, Wk, Wv, Wo, wqr, wkr, wvr, wor);

    // 1) projections (K,V outputs rounded to tf32 — they are B-side later)
    gemm2x<128, 128, false, 256, false><<<dim3(8, 16, 1), 256, 105984>>>(
        query, 0, 0, 0, 1024, wqr, 0, 0, 0, 1024, gq, 0, 0, 0, 1024,
        1024, bq, 1.f, 1, 1);
    gemm2x<128, 128, false, 256, true><<<dim3(8, 16, 1), 256, 105984>>>(
        key,   0, 0, 0, 1024, wkr, 0, 0, 0, 1024, gk, 0, 0, 0, 1024,
        1024, bk, 1.f, 1, 1);
    gemm2x<128, 128, false, 256, true><<<dim3(8, 16, 1), 256, 105984>>>(
        value, 0, 0, 0, 1024, wvr, 0, 0, 0, 1024, gv, 0, 0, 0, 1024,
        1024, bv, 1.f, 1, 1);

    // 2) scores per (b,h): S = Q K^T / 8 -> aw raw
    gemm2x<128, 128, true, 256, false><<<dim3(8, 8, 32), 256, 110592>>>(
        gq, 1048576, 64, 0, 1024,
        gk, 1048576, 64, 0, 1024,
        aw, 16777216LL, 1048576LL, 0, 1024,
        64, nullptr, 0.125f, 16, 32);

    // 3) masked softmax (block per (b,q))
    softmax_rows<<<2048, 512>>>(aw, mask);

    // 4) context per (b,h), split-K=2: partials -> g_cp, then reduce
    gemm2x<128, 64, false, 128, false><<<dim3(1, 8, 64), 128, 81408>>>(
        aw, 16777216LL, 1048576LL, 512, 1024,
        gv, 1048576, 64, 512LL * 1024, 1024,
        gp, 1048576, 64, 2097152, 1024,
        512, nullptr, 1.f, 16, 32);
    addhalves<<<2048, 256>>>(gp, gc);

    // 5) output projection: cv = ctx @ Wo + bo
    gemm2x<128, 128, false, 256, false><<<dim3(8, 16, 1), 256, 105984>>>(
        gc, 0, 0, 0, 1024, wor, 0, 0, 0, 1024, cv, 0, 0, 0, 1024,
        1024, bo, 1.f, 1, 1);
}

// round 6
// speedup vs baseline: 2.1951x; 1.3741x over previous
#include <cuda_runtime.h>
#include <cstdint>

// ----------------------------------------------------------------------------
// MultiheadAttention forward — pure 1xTF32 pipeline, all operands RNA-rounded.
//   prep    : round weights + inputs to tf32; pack biases
//   proj    : fused z=3 launch, Q/K/V projections, outputs rounded
//             layout: Q = qkv+0, K = qkv+M2, V = qkv+2*M2   (M2 = 2048*1024)
//   scores  : per (b,h) S = Q K^T / 8 (raw fp32)
//   softmax : block per (b,q), aw rounded to tf32 on store
//   context : split-K=2, partials; addhalves reduces + rounds ctx
//   outproj : BN=64 grid 256, cv = ctx @ Wo + bo
// ----------------------------------------------------------------------------

#define NEG_INF_F (__int_as_float(0xff7fffff))   // -FLT_MAX

static __device__ float g_qkv[3 * 2048 * 1024];   // rounded Q,K,V projections
static __device__ float g_rin[3 * 2048 * 1024];   // rounded inputs q,k,v
static __device__ float g_w  [3 * 1024 * 1024];   // rounded Wq,Wk,Wv
static __device__ float g_wo [1024 * 1024];       // rounded Wo
static __device__ float g_b3 [3 * 1024];          // packed biases bq,bk,bv
static __device__ float g_ctx[2048 * 1024];
static __device__ float g_cp [2 * 2048 * 1024];   // split-K partials

__device__ __forceinline__ uint32_t f2tf(float x) {
    uint32_t r;
    asm("cvt.rna.tf32.f32 %0, %1;" : "=r"(r) : "f"(x));
    return r;
}
__device__ __forceinline__ uint32_t s2u(const void* p) {
    return (uint32_t)__cvta_generic_to_shared(p);
}

#define CP_ASYNC16(dst, src) \
    asm volatile("cp.async.cg.shared.global [%0], [%1], 16;" :: "r"(dst), "l"(src))
#define CP_COMMIT() asm volatile("cp.async.commit_group;")
#define CP_WAIT1()  asm volatile("cp.async.wait_group 1;")

__device__ __forceinline__ void mma8(float c[4], const uint32_t a[4],
                                     uint32_t b0, uint32_t b1) {
    asm volatile(
        "mma.sync.aligned.m16n8k8.row.col.f32.tf32.tf32.f32 "
        "{%0,%1,%2,%3},{%4,%5,%6,%7},{%8,%9},{%0,%1,%2,%3};"
        : "+f"(c[0]), "+f"(c[1]), "+f"(c[2]), "+f"(c[3])
        : "r"(a[0]), "r"(a[1]), "r"(a[2]), "r"(a[3]), "r"(b0), "r"(b1));
}

#define R4V(v) v.x = __uint_as_float(f2tf(v.x)); v.y = __uint_as_float(f2tf(v.y)); \
               v.z = __uint_as_float(f2tf(v.z)); v.w = __uint_as_float(f2tf(v.w));

// Round 4 weight matrices (1M floats each, grid 1024x256).
__global__ __launch_bounds__(256) void round_w4(
    const float* __restrict__ a, const float* __restrict__ b,
    const float* __restrict__ c, const float* __restrict__ d,
    float* __restrict__ oa, float* __restrict__ ob,
    float* __restrict__ oc, float* __restrict__ od)
{
    int i = blockIdx.x * 256 + threadIdx.x;
    float4 va = ((const float4*)a)[i]; R4V(va) ((float4*)oa)[i] = va;
    float4 vb = ((const float4*)b)[i]; R4V(vb) ((float4*)ob)[i] = vb;
    float4 vc = ((const float4*)c)[i]; R4V(vc) ((float4*)oc)[i] = vc;
    float4 vd = ((const float4*)d)[i]; R4V(vd) ((float4*)od)[i] = vd;
}

// Round 3 input matrices (2M floats each, grid 2048x256).
__global__ __launch_bounds__(256) void round_in3(
    const float* __restrict__ a, const float* __restrict__ b,
    const float* __restrict__ c,
    float* __restrict__ oa, float* __restrict__ ob, float* __restrict__ oc)
{
    int i = blockIdx.x * 256 + threadIdx.x;
    float4 va = ((const float4*)a)[i]; R4V(va) ((float4*)oa)[i] = va;
    float4 vb = ((const float4*)b)[i]; R4V(vb) ((float4*)ob)[i] = vb;
    float4 vc = ((const float4*)c)[i]; R4V(vc) ((float4*)oc)[i] = vc;
}

// Pack 3 bias vectors (1024 each) contiguously. grid 12x256.
__global__ __launch_bounds__(256) void packb(
    const float* __restrict__ a, const float* __restrict__ b,
    const float* __restrict__ c, float* __restrict__ out)
{
    int i = blockIdx.x * 256 + threadIdx.x;         // < 3072
    int sel = i >> 10;
    const float* p = sel == 0 ? a : (sel == 1 ? b : c);
    out[i] = p[i & 1023];
}

// C = scale*A*op(B) + bias[bb*biasStride + col].
// NT=false: B [K,N] row-major; NT=true: B [N,K] row-major (C = A B^T).
// z -> (s = z/ZBH, r = z%ZBH, bb = r/H, hh = r%H); s adds split-K offsets.
// ALL A and B operand data must already be tf32-rounded (HW truncation lossless).
template <int BM, int BN, bool NT, int NTHREADS, bool ROUND>
__global__ __launch_bounds__(NTHREADS, 2) void gemm1x(
    const float* __restrict__ A, long long aB, long long aH, long long aS, int lda,
    const float* __restrict__ Bmat, long long bB, long long bH, long long bS, int ldb,
    float* __restrict__ C, long long cB, long long cH, long long cS, int ldc,
    int K, const float* __restrict__ bias, long long biasStride,
    float scale, int H, int ZBH)
{
    constexpr int BK = 32, STAGES = 3;
    constexpr int WARPS_M = BM / 64;          // warp tile 64x32
    constexpr int AP  = 36;
    constexpr int BNP = BN + 4;
    constexpr int ASZ = BM * AP;
    constexpr int BSZ = NT ? BN * AP : BK * BNP;

    extern __shared__ float sm[];
    float* sA = sm;
    float* sB = sm + STAGES * ASZ;

    const int z  = blockIdx.z;
    const int s  = z / ZBH;
    const int r0 = z - s * ZBH;
    const int bb = r0 / H, hh = r0 - bb * H;
    const float* Ap = A + (long long)bb * aB + (long long)hh * aH + (long long)s * aS
                        + (long long)blockIdx.y * BM * lda;
    const float* Bp;
    if (NT) Bp = Bmat + (long long)bb * bB + (long long)hh * bH + (long long)s * bS
                      + (long long)blockIdx.x * BN * ldb;
    else    Bp = Bmat + (long long)bb * bB + (long long)hh * bH + (long long)s * bS
                      + (long long)blockIdx.x * BN;
    float* Cp = C + (long long)bb * cB + (long long)hh * cH + (long long)s * cS;
    const float* bp = bias ? bias + (long long)bb * biasStride : nullptr;

    const int tid  = threadIdx.x;
    const int lane = tid & 31;
    const int wid  = tid >> 5;
    const int wm   = (wid % WARPS_M) * 64;
    const int wn   = (wid / WARPS_M) * 32;

    float acc[4][4][4];
#pragma unroll
    for (int i = 0; i < 4; i++)
#pragma unroll
        for (int j = 0; j < 4; j++)
#pragma unroll
            for (int c = 0; c < 4; c++) acc[i][j][c] = 0.f;

    auto load_tile = [&](int slot, int k0) {
        float* dA = sA + slot * ASZ;
        float* dB = sB + slot * BSZ;
#pragma unroll
        for (int i = 0; i < (BM * 8) / NTHREADS; i++) {
            int t = tid + i * NTHREADS;
            int r = t >> 3, c4 = (t & 7) * 4;
            CP_ASYNC16(s2u(dA + r * AP + c4), Ap + (long long)r * lda + k0 + c4);
        }
        if (NT) {
#pragma unroll
            for (int i = 0; i < (BN * 8) / NTHREADS; i++) {
                int t = tid + i * NTHREADS;
                int r = t >> 3, c4 = (t & 7) * 4;
                CP_ASYNC16(s2u(dB + r * AP + c4), Bp + (long long)r * ldb + k0 + c4);
            }
        } else {
#pragma unroll
            for (int i = 0; i < (BN * 8) / NTHREADS; i++) {
                int t = tid + i * NTHREADS;
                constexpr int C4 = BN / 4;
                int r = t / C4, c4 = (t - r * C4) * 4;
                CP_ASYNC16(s2u(dB + r * BNP + c4), Bp + (long long)(k0 + r) * ldb + c4);
            }
        }
    };

    auto compute = [&](int slot) {
        const float* cA = sA + slot * ASZ;
        const float* cB = sB + slot * BSZ;
#pragma unroll
        for (int ks = 0; ks < 4; ks++) {
            const int kb = ks * 8;
            uint32_t ah[4][4];
#pragma unroll
            for (int mt = 0; mt < 4; mt++) {
                int o = (wm + mt * 16 + (lane >> 2)) * AP + kb + (lane & 3);
                ah[mt][0] = __float_as_uint(cA[o]);
                ah[mt][1] = __float_as_uint(cA[o + 8 * AP]);
                ah[mt][2] = __float_as_uint(cA[o + 4]);
                ah[mt][3] = __float_as_uint(cA[o + 8 * AP + 4]);
            }
            uint32_t bh[4][2];
#pragma unroll
            for (int nt = 0; nt < 4; nt++) {
                int n  = wn + nt * 8 + (lane >> 2);
                int kk = kb + (lane & 3);
                if (NT) {
                    int o = n * AP + kk;
                    bh[nt][0] = __float_as_uint(cB[o]);
                    bh[nt][1] = __float_as_uint(cB[o + 4]);
                } else {
                    int o = kk * BNP + n;
                    bh[nt][0] = __float_as_uint(cB[o]);
                    bh[nt][1] = __float_as_uint(cB[o + 4 * BNP]);
                }
            }
#pragma unroll
            for (int mt = 0; mt < 4; mt++)
#pragma unroll
                for (int nt = 0; nt < 4; nt++)
                    mma8(acc[mt][nt], ah[mt], bh[nt][0], bh[nt][1]);
        }
    };

    const int kt_n = K / BK;
#pragma unroll
    for (int st = 0; st < STAGES - 1; st++) {
        if (st < kt_n) load_tile(st, st * BK);
        CP_COMMIT();
    }
    for (int kt = 0; kt < kt_n; kt++) {
        CP_WAIT1();
        __syncthreads();
        int nk = kt + STAGES - 1;
        if (nk < kt_n) load_tile(nk % STAGES, nk * BK);
        CP_COMMIT();
        compute(kt % STAGES);
    }

    const int row0 = blockIdx.y * BM + wm;
    const int col0 = blockIdx.x * BN + wn;
#pragma unroll
    for (int mt = 0; mt < 4; mt++) {
#pragma unroll
        for (int nt = 0; nt < 4; nt++) {
            int r = row0 + mt * 16 + (lane >> 2);
            int c = col0 + nt * 8 + 2 * (lane & 3);
            float b0 = bp ? bp[c]     : 0.f;
            float b1 = bp ? bp[c + 1] : 0.f;
            float o0 = acc[mt][nt][0] * scale + b0;
            float o1 = acc[mt][nt][1] * scale + b1;
            float o2 = acc[mt][nt][2] * scale + b0;
            float o3 = acc[mt][nt][3] * scale + b1;
            if (ROUND) {
                o0 = __uint_as_float(f2tf(o0));
                o1 = __uint_as_float(f2tf(o1));
                o2 = __uint_as_float(f2tf(o2));
                o3 = __uint_as_float(f2tf(o3));
            }
            *(float2*)(Cp + (long long)r * ldc + c)       = make_float2(o0, o1);
            *(float2*)(Cp + (long long)(r + 8) * ldc + c) = make_float2(o2, o3);
        }
    }
}

// Block = one (b,q); mask row in smem; 16 warps = 16 heads.
// aw rounded to tf32 on store (it is the context GEMM's A operand).
__global__ __launch_bounds__(512) void softmax_rows(
    float* __restrict__ aw, const int* __restrict__ mask)
{
    __shared__ int smask[1024];
    const int bq = blockIdx.x;                 // b*1024 + q
    const int b  = bq >> 10, q = bq & 1023;
    const int* mrow = mask + ((long long)bq << 10);
    if (threadIdx.x < 256)
        ((int4*)smask)[threadIdx.x] = ((const int4*)mrow)[threadIdx.x];
    __syncthreads();

    const int h    = threadIdx.x >> 5;
    const int lane = threadIdx.x & 31;
    float* arow = aw + ((long long)((b * 16 + h) * 1024 + q) << 10);

    float v[32];
    float m = NEG_INF_F;
#pragma unroll
    for (int j = 0; j < 8; j++) {
        int c = (lane + 32 * j) * 4;
        float4 f = __ldcs((const float4*)(arow + c));
        int4  mk = *(const int4*)(smask + c);
        v[4 * j + 0] = mk.x ? f.x : NEG_INF_F;
        v[4 * j + 1] = mk.y ? f.y : NEG_INF_F;
        v[4 * j + 2] = mk.z ? f.z : NEG_INF_F;
        v[4 * j + 3] = mk.w ? f.w : NEG_INF_F;
        m = fmaxf(m, fmaxf(fmaxf(v[4 * j], v[4 * j + 1]),
                           fmaxf(v[4 * j + 2], v[4 * j + 3])));
    }
#pragma unroll
    for (int o = 16; o > 0; o >>= 1) m = fmaxf(m, __shfl_xor_sync(0xffffffffu, m, o));
    float s = 0.f;
#pragma unroll
    for (int i = 0; i < 32; i++) { float e = __expf(v[i] - m); v[i] = e; s += e; }
#pragma unroll
    for (int o = 16; o > 0; o >>= 1) s += __shfl_xor_sync(0xffffffffu, s, o);
    float inv = 1.f / s;
#pragma unroll
    for (int j = 0; j < 8; j++) {
        int c = (lane + 32 * j) * 4;
        float4 o4 = make_float4(v[4 * j] * inv, v[4 * j + 1] * inv,
                                v[4 * j + 2] * inv, v[4 * j + 3] * inv);
        R4V(o4)
        __stcs((float4*)(arow + c), o4);
    }
}

// ctx = round_tf32(partial0 + partial1), 2M floats (grid 2048x256).
__global__ __launch_bounds__(256) void addhalves(
    const float* __restrict__ p, float* __restrict__ ctx)
{
    int i = blockIdx.x * 256 + threadIdx.x;
    float4 a = ((const float4*)p)[i];
    float4 b = ((const float4*)(p + 2097152))[i];
    float4 o = make_float4(a.x + b.x, a.y + b.y, a.z + b.z, a.w + b.w);
    R4V(o)
    ((float4*)ctx)[i] = o;
}

extern "C" void kernel_launch(void* const* d_in, const int* in_sizes, int n_in,
                              void* d_out, int out_size)
{
    const float* key   = (const float*)d_in[0];
    const float* value = (const float*)d_in[1];
    const float* query = (const float*)d_in[2];
    const int*   mask  = (const int*)d_in[3];
    const float* Wk = (const float*)d_in[4];
    const float* bk = (const float*)d_in[5];
    const float* Wv = (const float*)d_in[6];
    const float* bv = (const float*)d_in[7];
    const float* Wq = (const float*)d_in[8];
    const float* bq = (const float*)d_in[9];
    const float* Wo = (const float*)d_in[10];
    const float* bo = (const float*)d_in[11];

    float* cv = (float*)d_out;                    // [2, 1024, 1024]
    float* aw = cv + 2LL * 1024 * 1024;           // [2, 16, 1024, 1024]

    float *qkv, *rin, *w3, *wo3, *b3, *gc, *gp;
    cudaGetSymbolAddress((void**)&qkv, g_qkv);
    cudaGetSymbolAddress((void**)&rin, g_rin);
    cudaGetSymbolAddress((void**)&w3,  g_w);
    cudaGetSymbolAddress((void**)&wo3, g_wo);
    cudaGetSymbolAddress((void**)&b3,  g_b3);
    cudaGetSymbolAddress((void**)&gc,  g_ctx);
    cudaGetSymbolAddress((void**)&gp,  g_cp);

    cudaFuncSetAttribute((const void*)gemm1x<128, 128, false, 256, true>,
                         cudaFuncAttributeMaxDynamicSharedMemorySize, 105984);
    cudaFuncSetAttribute((const void*)gemm1x<128, 128, true, 256, false>,
                         cudaFuncAttributeMaxDynamicSharedMemorySize, 110592);
    cudaFuncSetAttribute((const void*)gemm1x<128, 64, false, 128, false>,
                         cudaFuncAttributeMaxDynamicSharedMemorySize, 81408);

    const long long M2 = 2097152, M1 = 1048576;
    float* Qp = qkv;              // [2048,1024] rounded Q
    float* Kp = qkv + M2;         // [2048,1024] rounded K
    float* Vp = qkv + 2 * M2;     // [2048,1024] rounded V

    // 0) prep: round weights (Wq,Wk,Wv -> g_w slices; Wo), inputs, pack biases
    round_w4<<<1024, 256>>>(Wq, Wk, Wv, Wo, w3, w3 + M1, w3 + 2 * M1, wo3);
    round_in3<<<2048, 256>>>(query, key, value, rin, rin + M2, rin + 2 * M2);
    packb<<<12, 256>>>(bq, bk, bv, b3);

    // 1) fused projections: z=0,1,2 -> Q,K,V (all outputs tf32-rounded)
    gemm1x<128, 128, false, 256, true><<<dim3(8, 16, 3), 256, 105984>>>(
        rin, M2, 0, 0, 1024,
        w3,  M1, 0, 0, 1024,
        qkv, M2, 0, 0, 1024,
        1024, b3, 1024, 1.f, 1, 3);

    // 2) scores per (b,h): S = Q K^T / 8 -> aw raw fp32   (B = K !)
    gemm1x<128, 128, true, 256, false><<<dim3(8, 8, 32), 256, 110592>>>(
        Qp, M1, 64, 0, 1024,
        Kp, M1, 64, 0, 1024,
        aw, 16777216LL, 1048576LL, 0, 1024,
        64, nullptr, 0, 0.125f, 16, 32);

    // 3) masked softmax (block per (b,q)); aw rounded to tf32
    softmax_rows<<<2048, 512>>>(aw, mask);

    // 4) context per (b,h), split-K=2 -> partials, then reduce (+round ctx)
    //    (B = V !)
    gemm1x<128, 64, false, 128, false><<<dim3(1, 8, 64), 128, 81408>>>(
        aw, 16777216LL, 1048576LL, 512, 1024,
        Vp, M1, 64, 512LL * 1024, 1024,
        gp, M1, 64, M2, 1024,
        512, nullptr, 0, 1.f, 16, 32);
    addhalves<<<2048, 256>>>(gp, gc);

    // 5) output projection: cv = ctx @ Wo + bo  (BN=64, grid 256)
    gemm1x<128, 64, false, 128, false><<<dim3(16, 16, 1), 128, 81408>>>(
        gc,  0, 0, 0, 1024,
        wo3, 0, 0, 0, 1024,
        cv,  0, 0, 0, 1024,
        1024, bo, 0, 1.f, 1, 1);
}